// round 3
// baseline (speedup 1.0000x reference)
#include <cuda_runtime.h>
#include <math.h>

// ============================================================
// EGNN layer, N=50000, E=800000, D=128
// Round-2 fix: edge_index dtype. The harness only supports
// {float32,int32,bf16}; int64 edge_index is (almost certainly)
// delivered as int32. Reading it as long long ran 6.4MB past the
// allocation -> the illegal memory access. We now probe the layout
// on-device (int64 little-endian high words are all zero) and
// decode sender/receiver into int scratch, in-bounds either way.
//
// Structure: fused edge MLP (gather + 2x GEMM + silu + v4-red
// scatter) + node MLP (2x GEMM + silu + residual).
// GEMMs: 128x128 CTA tile, 8x8 thread tile, 256 threads.
// ============================================================

#define DD      128
#define BM      128
#define BK      32
#define APITCH  136            // 128 + 8 pad; row stride 544B (16B multiple)
#define NMAX    50000
#define EMAX    800000

__device__ __align__(16) float g_agg[(size_t)NMAX * DD];
__device__ __align__(16) float g_W1t[257 * DD];      // W1t[k][j] = W1[j][k]
__device__ __align__(16) float g_W2t[DD * DD];
__device__ __align__(16) float g_U1t[2 * DD * DD];
__device__ __align__(16) float g_U2t[DD * DD];
__device__ int g_sidx[EMAX];
__device__ int g_ridx[EMAX];
__device__ int g_is64;

struct __align__(16) TileSmem {
    float A0[BM][APITCH];   // sender h tile (later: m tile)
    float A1[BM][APITCH];   // receiver h tile (node kernel: agg tile)
    float Bs[BK][DD];
    float dist[BM];
    int   ridx[BM];
};

__device__ __forceinline__ float silu_f(float x) {
    return x * (1.0f / (1.0f + __expf(-x)));
}

__device__ __forceinline__ void red_add_v4(float* p, float a, float b, float c, float d) {
    asm volatile("red.global.add.v4.f32 [%0], {%1,%2,%3,%4};"
                 :: "l"(p), "f"(a), "f"(b), "f"(c), "f"(d) : "memory");
}

// ---- edge_index layout probe + decode ----
// int64 little-endian with values < 2^31: every odd int32 word is 0.
__global__ void detect_kernel(const int* __restrict__ ei32) {
    if (threadIdx.x == 0) {
        int any = 0;
        #pragma unroll
        for (int i = 1; i < 64; i += 2) any |= ei32[i];
        g_is64 = (any == 0) ? 1 : 0;
    }
}

__global__ void decode_kernel(const int* __restrict__ ei32, int E) {
    int e = blockIdx.x * blockDim.x + threadIdx.x;
    if (e < E) {
        if (g_is64) {                      // buffer is int64[2*E] = int32[4*E]
            g_sidx[e] = ei32[2 * e];
            g_ridx[e] = ei32[2 * E + 2 * e];
        } else {                           // buffer is int32[2*E]
            g_sidx[e] = ei32[e];
            g_ridx[e] = ei32[E + e];
        }
    }
}

__global__ void zero_agg_kernel(int n4) {
    int i = blockIdx.x * blockDim.x + threadIdx.x;
    int stride = gridDim.x * blockDim.x;
    float4* p = reinterpret_cast<float4*>(g_agg);
    float4 z = make_float4(0.f, 0.f, 0.f, 0.f);
    for (int t = i; t < n4; t += stride) p[t] = z;
}

// dst[k*J + j] = src[j*K + k]
__global__ void transpose_into_kernel(const float* __restrict__ src, int which, int J, int K) {
    float* dst = (which == 0) ? g_W1t : (which == 1) ? g_W2t : (which == 2) ? g_U1t : g_U2t;
    int idx = blockIdx.x * blockDim.x + threadIdx.x;
    if (idx < J * K) {
        int k = idx / J;
        int j = idx - k * J;
        dst[idx] = src[j * K + k];
    }
}

// ---------------- shared GEMM inner loop ----------------
__device__ __forceinline__ void gemm_chunk(const float (*A)[APITCH], const float (*Bs)[DD],
                                           int ty, int tx, int kbase, float acc[8][8]) {
    #pragma unroll
    for (int k4 = 0; k4 < BK / 4; ++k4) {
        float4 a4[8];
        #pragma unroll
        for (int i = 0; i < 8; ++i)
            a4[i] = *reinterpret_cast<const float4*>(&A[ty * 8 + i][kbase + k4 * 4]);
        #pragma unroll
        for (int kk = 0; kk < 4; ++kk) {
            int k = k4 * 4 + kk;
            float4 b0 = *reinterpret_cast<const float4*>(&Bs[k][tx * 8]);
            float4 b1 = *reinterpret_cast<const float4*>(&Bs[k][tx * 8 + 4]);
            float b[8] = {b0.x, b0.y, b0.z, b0.w, b1.x, b1.y, b1.z, b1.w};
            #pragma unroll
            for (int i = 0; i < 8; ++i) {
                float a = reinterpret_cast<const float*>(&a4[i])[kk];
                #pragma unroll
                for (int j = 0; j < 8; ++j)
                    acc[i][j] = fmaf(a, b[j], acc[i][j]);
            }
        }
    }
}

__device__ __forceinline__ void load_B_chunk(float (*Bs)[DD], const float* __restrict__ Wt,
                                             int kb, int tid) {
    const float4* W4 = reinterpret_cast<const float4*>(Wt + kb * BK * DD);
    float4* B4 = reinterpret_cast<float4*>(&Bs[0][0]);
    #pragma unroll
    for (int i = 0; i < (BK * DD / 4) / 256; ++i)
        B4[tid + i * 256] = W4[tid + i * 256];
}

// ---------------- edge kernel ----------------
__global__ __launch_bounds__(256, 1)
void edge_kernel(const float* __restrict__ h, const float* __restrict__ coords,
                 const float* __restrict__ b1, const float* __restrict__ b2,
                 int N, int E) {
    extern __shared__ __align__(16) char smem_raw[];
    TileSmem& S = *reinterpret_cast<TileSmem*>(smem_raw);
    const int tid = threadIdx.x;
    const int tx = tid & 15, ty = tid >> 4;
    const int e0 = blockIdx.x * BM;

    // per-tile indices + dist (sidx parked in S.ridx slot temporarily? no:
    // keep sidx in registers of the first 128 threads via smem arrays)
    __shared__ int s_sidx[BM];
    if (tid < BM) {
        int e = e0 + tid;
        int s = 0, r = 0;
        float d = 0.f;
        if (e < E) {
            s = g_sidx[e];
            r = g_ridx[e];
            float dx = coords[3 * s]     - coords[3 * r];
            float dy = coords[3 * s + 1] - coords[3 * r + 1];
            float dz = coords[3 * s + 2] - coords[3 * r + 2];
            d = sqrtf(dx * dx + dy * dy + dz * dz);
        }
        s_sidx[tid] = s;
        S.ridx[tid] = r;
        S.dist[tid] = d;
    }
    __syncthreads();

    // stage sender / receiver h rows (gathers; h is L2-resident)
    const float4* h4 = reinterpret_cast<const float4*>(h);
    for (int t = tid; t < BM * (DD / 4); t += 256) {
        int e = t >> 5, q = t & 31;
        float4 v = h4[(size_t)s_sidx[e] * (DD / 4) + q];
        float4 w = h4[(size_t)S.ridx[e] * (DD / 4) + q];
        *reinterpret_cast<float4*>(&S.A0[e][q * 4]) = v;
        *reinterpret_cast<float4*>(&S.A1[e][q * 4]) = w;
    }
    __syncthreads();

    float acc[8][8];
    #pragma unroll
    for (int i = 0; i < 8; ++i)
        #pragma unroll
        for (int j = 0; j < 8; ++j) acc[i][j] = 0.f;

    // ---- layer 1: acc = h_s @ W1a^T + h_r @ W1b^T  (K = 128 each) ----
    #pragma unroll 1
    for (int part = 0; part < 2; ++part) {
        const float (*A)[APITCH] = (part == 0) ? S.A0 : S.A1;
        const float* Wt = g_W1t + part * DD * DD;
        #pragma unroll 1
        for (int kb = 0; kb < DD / BK; ++kb) {
            load_B_chunk(S.Bs, Wt, kb, tid);
            __syncthreads();
            gemm_chunk(A, S.Bs, ty, tx, kb * BK, acc);
            __syncthreads();
        }
    }

    // epilogue 1: + dist * W1[:,256] + b1, silu
    {
        float wl[8], bb[8];
        #pragma unroll
        for (int j = 0; j < 8; ++j) {
            wl[j] = g_W1t[256 * DD + tx * 8 + j];
            bb[j] = b1[tx * 8 + j];
        }
        #pragma unroll
        for (int i = 0; i < 8; ++i) {
            float d = S.dist[ty * 8 + i];
            #pragma unroll
            for (int j = 0; j < 8; ++j)
                acc[i][j] = silu_f(acc[i][j] + d * wl[j] + bb[j]);
        }
    }
    // write m tile into A0 (everyone is past the last layer-1 sync)
    #pragma unroll
    for (int i = 0; i < 8; ++i)
        #pragma unroll
        for (int j = 0; j < 8; ++j)
            S.A0[ty * 8 + i][tx * 8 + j] = acc[i][j];
    __syncthreads();

    // ---- layer 2: z = m @ W2^T ----
    #pragma unroll
    for (int i = 0; i < 8; ++i)
        #pragma unroll
        for (int j = 0; j < 8; ++j) acc[i][j] = 0.f;

    #pragma unroll 1
    for (int kb = 0; kb < DD / BK; ++kb) {
        load_B_chunk(S.Bs, g_W2t, kb, tid);
        __syncthreads();
        gemm_chunk(S.A0, S.Bs, ty, tx, kb * BK, acc);
        __syncthreads();
    }

    // epilogue 2: + b2, silu, vector-atomic scatter into agg[receiver]
    {
        float bb[8];
        #pragma unroll
        for (int j = 0; j < 8; ++j) bb[j] = b2[tx * 8 + j];
        #pragma unroll
        for (int i = 0; i < 8; ++i) {
            int er = ty * 8 + i;
            if (e0 + er < E) {
                float z[8];
                #pragma unroll
                for (int j = 0; j < 8; ++j) z[j] = silu_f(acc[i][j] + bb[j]);
                float* dst = g_agg + (size_t)S.ridx[er] * DD + tx * 8;
                red_add_v4(dst,     z[0], z[1], z[2], z[3]);
                red_add_v4(dst + 4, z[4], z[5], z[6], z[7]);
            }
        }
    }
}

// ---------------- node kernel ----------------
__global__ __launch_bounds__(256, 1)
void node_kernel(const float* __restrict__ h,
                 const float* __restrict__ c1, const float* __restrict__ c2,
                 float* __restrict__ out, int N) {
    extern __shared__ __align__(16) char smem_raw[];
    TileSmem& S = *reinterpret_cast<TileSmem*>(smem_raw);
    const int tid = threadIdx.x;
    const int tx = tid & 15, ty = tid >> 4;
    const int n0 = blockIdx.x * BM;

    const float4* h4 = reinterpret_cast<const float4*>(h);
    const float4* a4g = reinterpret_cast<const float4*>(g_agg);
    float4 zf = make_float4(0.f, 0.f, 0.f, 0.f);
    for (int t = tid; t < BM * (DD / 4); t += 256) {
        int e = t >> 5, q = t & 31;
        int n = n0 + e;
        float4 v = (n < N) ? h4[(size_t)n * (DD / 4) + q] : zf;
        float4 w = (n < N) ? a4g[(size_t)n * (DD / 4) + q] : zf;
        *reinterpret_cast<float4*>(&S.A0[e][q * 4]) = v;
        *reinterpret_cast<float4*>(&S.A1[e][q * 4]) = w;
    }
    __syncthreads();

    float acc[8][8];
    #pragma unroll
    for (int i = 0; i < 8; ++i)
        #pragma unroll
        for (int j = 0; j < 8; ++j) acc[i][j] = 0.f;

    // ---- layer 1: h @ U1a^T + agg @ U1b^T ----
    #pragma unroll 1
    for (int part = 0; part < 2; ++part) {
        const float (*A)[APITCH] = (part == 0) ? S.A0 : S.A1;
        const float* Wt = g_U1t + part * DD * DD;
        #pragma unroll 1
        for (int kb = 0; kb < DD / BK; ++kb) {
            load_B_chunk(S.Bs, Wt, kb, tid);
            __syncthreads();
            gemm_chunk(A, S.Bs, ty, tx, kb * BK, acc);
            __syncthreads();
        }
    }

    // epilogue 1: + c1, silu, store y into A0
    {
        float bb[8];
        #pragma unroll
        for (int j = 0; j < 8; ++j) bb[j] = c1[tx * 8 + j];
        #pragma unroll
        for (int i = 0; i < 8; ++i)
            #pragma unroll
            for (int j = 0; j < 8; ++j)
                S.A0[ty * 8 + i][tx * 8 + j] = silu_f(acc[i][j] + bb[j]);
    }
    __syncthreads();

    // ---- layer 2: y @ U2^T ----
    #pragma unroll
    for (int i = 0; i < 8; ++i)
        #pragma unroll
        for (int j = 0; j < 8; ++j) acc[i][j] = 0.f;

    #pragma unroll 1
    for (int kb = 0; kb < DD / BK; ++kb) {
        load_B_chunk(S.Bs, g_U2t, kb, tid);
        __syncthreads();
        gemm_chunk(S.A0, S.Bs, ty, tx, kb * BK, acc);
        __syncthreads();
    }

    // epilogue 2: out = h + (z + c2)
    {
        float bb[8];
        #pragma unroll
        for (int j = 0; j < 8; ++j) bb[j] = c2[tx * 8 + j];
        #pragma unroll
        for (int i = 0; i < 8; ++i) {
            int n = n0 + ty * 8 + i;
            if (n < N) {
                const float* hrow = h + (size_t)n * DD + tx * 8;
                float* orow = out + (size_t)n * DD + tx * 8;
                float4 h0 = *reinterpret_cast<const float4*>(hrow);
                float4 h1 = *reinterpret_cast<const float4*>(hrow + 4);
                float4 o0, o1;
                o0.x = h0.x + acc[i][0] + bb[0];
                o0.y = h0.y + acc[i][1] + bb[1];
                o0.z = h0.z + acc[i][2] + bb[2];
                o0.w = h0.w + acc[i][3] + bb[3];
                o1.x = h1.x + acc[i][4] + bb[4];
                o1.y = h1.y + acc[i][5] + bb[5];
                o1.z = h1.z + acc[i][6] + bb[6];
                o1.w = h1.w + acc[i][7] + bb[7];
                *reinterpret_cast<float4*>(orow) = o0;
                *reinterpret_cast<float4*>(orow + 4) = o1;
            }
        }
    }
}

// ---------------- launch ----------------
extern "C" void kernel_launch(void* const* d_in, const int* in_sizes, int n_in,
                              void* d_out, int out_size) {
    const float* h      = (const float*)d_in[0];
    const float* coords = (const float*)d_in[1];
    const int*   ei32   = (const int*)d_in[2];     // int32 OR int64 bits; probed on device
    const float* W1     = (const float*)d_in[3];
    const float* b1     = (const float*)d_in[4];
    const float* W2     = (const float*)d_in[5];
    const float* b2     = (const float*)d_in[6];
    const float* U1     = (const float*)d_in[7];
    const float* c1     = (const float*)d_in[8];
    const float* U2     = (const float*)d_in[9];
    const float* c2     = (const float*)d_in[10];
    float* out = (float*)d_out;

    const int N = in_sizes[0] / DD;
    const int E = in_sizes[2] / 2;

    size_t smem = sizeof(TileSmem);
    cudaFuncSetAttribute(edge_kernel, cudaFuncAttributeMaxDynamicSharedMemorySize, (int)smem);
    cudaFuncSetAttribute(node_kernel, cudaFuncAttributeMaxDynamicSharedMemorySize, (int)smem);

    // 0) probe edge_index layout + decode into int scratch
    detect_kernel<<<1, 32>>>(ei32);
    decode_kernel<<<(E + 255) / 256, 256>>>(ei32, E);

    // 1) zero aggregation buffer
    zero_agg_kernel<<<512, 256>>>(N * DD / 4);

    // 2) transpose weights into device scratch (coalesced B reads later)
    transpose_into_kernel<<<(DD * 257 + 255) / 256, 256>>>(W1, 0, DD, 257);
    transpose_into_kernel<<<(DD * DD  + 255) / 256, 256>>>(W2, 1, DD, DD);
    transpose_into_kernel<<<(DD * 256 + 255) / 256, 256>>>(U1, 2, DD, 256);
    transpose_into_kernel<<<(DD * DD  + 255) / 256, 256>>>(U2, 3, DD, DD);

    // 3) fused edge MLP + scatter
    edge_kernel<<<(E + BM - 1) / BM, 256, smem>>>(h, coords, b1, b2, N, E);

    // 4) node MLP + residual
    node_kernel<<<(N + BM - 1) / BM, 256, smem>>>(h, c1, c2, out, N);
}